// round 8
// baseline (speedup 1.0000x reference)
#include <cuda_runtime.h>
#include <cuda_fp16.h>
#include <math.h>

#define MAX_N 100000
#define MAX_E 1600000
#define D 64
#define SCAN_B 1024
#define DEG_CAP 160          // per-warp smem ex cache (max Poisson(16) deg ~50)

// ---- device scratch (no cudaMalloc allowed) --------------------------------
// g_count is zero-initialized at module load; scatter_kernel re-zeroes it at
// every launch (after its last reader ran), so every launch sees zeros.
__device__ float g_q[MAX_N * D];
__device__ uint4 g_kv[MAX_N * 16];      // per node: 16 x uint4 = 64 (k,v) half-pairs
__device__ int   g_count[MAX_N + 1];
__device__ int   g_rowptr[MAX_N + 1];
__device__ int   g_cursor[MAX_N + 1];
__device__ int   g_bsum[128];
__device__ int2  g_edges[MAX_E];        // (src, orig_eid) clustered by dst
__device__ float g_ex[MAX_E];           // fallback if out has no alpha slot

// ---------------------------------------------------------------------------
// K1: q,k,v = z @ W{q,k,v} + b.  q fp32; k (pre-scaled by tau) and v packed as
// interleaved fp16 pairs -> ONE 16B vector per lane per edge in fused kernel.
// ---------------------------------------------------------------------------
__global__ __launch_bounds__(256) void proj_kernel(
    const float* __restrict__ z,
    const float* __restrict__ Wq, const float* __restrict__ bq,
    const float* __restrict__ Wk, const float* __restrict__ bk,
    const float* __restrict__ Wv, const float* __restrict__ bv,
    int n)
{
    __shared__ __align__(16) float zsh[64 * 68];   // transposed: zsh[k*68 + node]
    __shared__ __align__(16) float wsh[64 * 64];   // wsh[k*64 + dim]

    const int tid = threadIdx.x;
    const int node0 = blockIdx.x * 64;

    for (int i = tid; i < 64 * 64; i += 256) {
        int nn = i >> 6, kk = i & 63;
        int g = node0 + nn;
        zsh[kk * 68 + nn] = (g < n) ? z[(size_t)g * D + kk] : 0.0f;
    }

    const float* Ws[3] = {Wq, Wk, Wv};
    const float* bs[3] = {bq, bk, bv};

    const int ng = tid >> 4;   // node group 0..15 (4 nodes)
    const int dg = tid & 15;   // dim  group 0..15 (4 dims)

    float kacc[4][4];          // k results held across passes (scaled by tau)

    for (int p = 0; p < 3; p++) {
        __syncthreads();
        const float* W = Ws[p];
        for (int i = tid; i < 64 * 64; i += 256) wsh[i] = W[i];
        __syncthreads();

        float4 b4 = *(const float4*)(bs[p] + dg * 4);
        float acc[4][4];
        #pragma unroll
        for (int i2 = 0; i2 < 4; i2++) {
            acc[i2][0] = b4.x; acc[i2][1] = b4.y; acc[i2][2] = b4.z; acc[i2][3] = b4.w;
        }

        #pragma unroll 8
        for (int k = 0; k < 64; k++) {
            float4 zv = *(const float4*)&zsh[k * 68 + ng * 4];
            float4 wv = *(const float4*)&wsh[k * 64 + dg * 4];
            acc[0][0] += zv.x * wv.x; acc[0][1] += zv.x * wv.y; acc[0][2] += zv.x * wv.z; acc[0][3] += zv.x * wv.w;
            acc[1][0] += zv.y * wv.x; acc[1][1] += zv.y * wv.y; acc[1][2] += zv.y * wv.z; acc[1][3] += zv.y * wv.w;
            acc[2][0] += zv.z * wv.x; acc[2][1] += zv.z * wv.y; acc[2][2] += zv.z * wv.z; acc[2][3] += zv.z * wv.w;
            acc[3][0] += zv.w * wv.x; acc[3][1] += zv.w * wv.y; acc[3][2] += zv.w * wv.z; acc[3][3] += zv.w * wv.w;
        }

        if (p == 0) {                 // q -> fp32
            #pragma unroll
            for (int i2 = 0; i2 < 4; i2++) {
                int g = node0 + ng * 4 + i2;
                if (g < n)
                    *(float4*)(g_q + (size_t)g * D + dg * 4) =
                        make_float4(acc[i2][0], acc[i2][1], acc[i2][2], acc[i2][3]);
            }
        } else if (p == 1) {          // k -> registers, pre-scaled by tau
            #pragma unroll
            for (int i2 = 0; i2 < 4; i2++)
                #pragma unroll
                for (int j = 0; j < 4; j++)
                    kacc[i2][j] = acc[i2][j] * 0.125f;
        } else {                      // v: pack (k,v) half pairs, one uint4/node
            #pragma unroll
            for (int i2 = 0; i2 < 4; i2++) {
                int g = node0 + ng * 4 + i2;
                if (g < n) {
                    uint4 pk;
                    __half2 h0 = __float22half2_rn(make_float2(kacc[i2][0], acc[i2][0]));
                    __half2 h1 = __float22half2_rn(make_float2(kacc[i2][1], acc[i2][1]));
                    __half2 h2 = __float22half2_rn(make_float2(kacc[i2][2], acc[i2][2]));
                    __half2 h3 = __float22half2_rn(make_float2(kacc[i2][3], acc[i2][3]));
                    pk.x = *(unsigned*)&h0; pk.y = *(unsigned*)&h1;
                    pk.z = *(unsigned*)&h2; pk.w = *(unsigned*)&h3;
                    g_kv[(size_t)g * 16 + dg] = pk;
                }
            }
        }
    }
}

// ---------------------------------------------------------------------------
// CSR build: hist (int4) -> scan1 (block sums) -> scan3 (scan + per-block
// redundant bsum prefix; scan2 eliminated) -> scatter (int4, also re-zeroes
// g_count for the next launch).
// ---------------------------------------------------------------------------
__global__ void hist_kernel(const int* __restrict__ dst, int E) {
    int e = (blockIdx.x * blockDim.x + threadIdx.x) * 4;
    if (e + 3 < E) {
        int4 d = *(const int4*)(dst + e);
        atomicAdd(&g_count[d.x], 1);
        atomicAdd(&g_count[d.y], 1);
        atomicAdd(&g_count[d.z], 1);
        atomicAdd(&g_count[d.w], 1);
    } else {
        for (int t = e; t < E; t++) atomicAdd(&g_count[dst[t]], 1);
    }
}

__global__ __launch_bounds__(SCAN_B) void scan1_kernel(int len) {
    __shared__ int wsum[32];
    int t = threadIdx.x, lane = t & 31, wid = t >> 5;
    int i = blockIdx.x * SCAN_B + t;
    int v = (i < len) ? g_count[i] : 0;
    #pragma unroll
    for (int off = 16; off > 0; off >>= 1) v += __shfl_xor_sync(0xffffffffu, v, off);
    if (lane == 0) wsum[wid] = v;
    __syncthreads();
    if (wid == 0) {
        int x = wsum[lane];
        #pragma unroll
        for (int off = 16; off > 0; off >>= 1) x += __shfl_xor_sync(0xffffffffu, x, off);
        if (lane == 0) g_bsum[blockIdx.x] = x;
    }
}

__global__ __launch_bounds__(SCAN_B) void scan3_kernel(int len) {
    __shared__ int wsum[32];
    __shared__ int blk_off;
    int t = threadIdx.x, lane = t & 31, wid = t >> 5;

    // warp 0: exclusive prefix of block sums for this block (<=98 entries)
    if (wid == 0) {
        int s = 0;
        for (int b = lane; b < blockIdx.x; b += 32) s += g_bsum[b];
        #pragma unroll
        for (int off = 16; off > 0; off >>= 1) s += __shfl_xor_sync(0xffffffffu, s, off);
        if (lane == 0) blk_off = s;
    }

    int i = blockIdx.x * SCAN_B + t;
    int v = (i < len) ? g_count[i] : 0;
    int incl = v;
    #pragma unroll
    for (int off = 1; off < 32; off <<= 1) {
        int u = __shfl_up_sync(0xffffffffu, incl, off);
        if (lane >= off) incl += u;
    }
    if (lane == 31) wsum[wid] = incl;
    __syncthreads();
    if (wid == 0) {
        int x = wsum[lane];
        #pragma unroll
        for (int off = 1; off < 32; off <<= 1) {
            int u = __shfl_up_sync(0xffffffffu, x, off);
            if (lane >= off) x += u;
        }
        wsum[lane] = x;
    }
    __syncthreads();
    int excl = incl - v + ((wid > 0) ? wsum[wid - 1] : 0) + blk_off;
    if (i < len) { g_rowptr[i] = excl; g_cursor[i] = excl; }
}

__global__ void scatter_kernel(const int* __restrict__ src,
                               const int* __restrict__ dst, int E, int n) {
    int gt = blockIdx.x * blockDim.x + threadIdx.x;
    // re-zero the histogram for the next launch (last reader was scan3)
    if (gt <= n) g_count[gt] = 0;

    int e = gt * 4;
    if (e + 3 < E) {
        int4 s = *(const int4*)(src + e);
        int4 d = *(const int4*)(dst + e);
        int p0 = atomicAdd(&g_cursor[d.x], 1);
        int p1 = atomicAdd(&g_cursor[d.y], 1);
        int p2 = atomicAdd(&g_cursor[d.z], 1);
        int p3 = atomicAdd(&g_cursor[d.w], 1);
        g_edges[p0] = make_int2(s.x, e + 0);
        g_edges[p1] = make_int2(s.y, e + 1);
        g_edges[p2] = make_int2(s.z, e + 2);
        g_edges[p3] = make_int2(s.w, e + 3);
    } else {
        for (int t = e; t < E; t++) {
            int pos = atomicAdd(&g_cursor[dst[t]], 1);
            g_edges[pos] = make_int2(src[t], t);
        }
    }
}

// ---------------------------------------------------------------------------
// K2 (fused): one warp per dst node; each half-warp handles 4 edges per
// iteration (8/warp) -> 8 independent 256B kv gathers in flight per warp.
// One 16B (k,v)-pair load per lane per edge; dot in fp32 (tau folded into k);
// ex cached in per-warp smem (global fallback). NO atomics.
// Segment-max skipped: alpha shift-invariant, |e|<~6 -> exp safe.
// ---------------------------------------------------------------------------
__global__ __launch_bounds__(256) void fused_attn_kernel(
    float* __restrict__ exbuf, float* __restrict__ h, int n)
{
    __shared__ float s_ex[8][DEG_CAP];

    int wid = threadIdx.x >> 5;
    int w = blockIdx.x * 8 + wid;
    if (w >= n) return;
    int lane = threadIdx.x & 31;
    int half = lane >> 4;
    int li   = lane & 15;
    unsigned hmask = 0xFFFFu << (half * 16);

    int beg = __ldg(&g_rowptr[w]);
    int end = __ldg(&g_rowptr[w + 1]);
    int cnt = end - beg;

    float4 qv = *(const float4*)(g_q + (size_t)w * D + li * 4);

    float den = 0.0f;
    float4 acc = make_float4(0.f, 0.f, 0.f, 0.f);

    for (int i = beg + half; i < end; i += 8) {
        bool ok1 = (i + 2) < end;
        bool ok2 = (i + 4) < end;
        bool ok3 = (i + 6) < end;

        // 4 independent edge-record loads (uniform per half-warp)
        int2 E0 = g_edges[i];
        int2 E1 = g_edges[ok1 ? i + 2 : i];
        int2 E2 = g_edges[ok2 ? i + 4 : i];
        int2 E3 = g_edges[ok3 ? i + 6 : i];

        // 4 independent 256B row gathers
        uint4 a0 = g_kv[(size_t)E0.x * 16 + li];
        uint4 a1 = g_kv[(size_t)E1.x * 16 + li];
        uint4 a2 = g_kv[(size_t)E2.x * 16 + li];
        uint4 a3 = g_kv[(size_t)E3.x * 16 + li];

        float2 p00 = __half22float2(*(__half2*)&a0.x), p01 = __half22float2(*(__half2*)&a0.y);
        float2 p02 = __half22float2(*(__half2*)&a0.z), p03 = __half22float2(*(__half2*)&a0.w);
        float2 p10 = __half22float2(*(__half2*)&a1.x), p11 = __half22float2(*(__half2*)&a1.y);
        float2 p12 = __half22float2(*(__half2*)&a1.z), p13 = __half22float2(*(__half2*)&a1.w);
        float2 p20 = __half22float2(*(__half2*)&a2.x), p21 = __half22float2(*(__half2*)&a2.y);
        float2 p22 = __half22float2(*(__half2*)&a2.z), p23 = __half22float2(*(__half2*)&a2.w);
        float2 p30 = __half22float2(*(__half2*)&a3.x), p31 = __half22float2(*(__half2*)&a3.y);
        float2 p32 = __half22float2(*(__half2*)&a3.z), p33 = __half22float2(*(__half2*)&a3.w);

        float s0 = p00.x * qv.x + p01.x * qv.y + p02.x * qv.z + p03.x * qv.w;
        float s1 = p10.x * qv.x + p11.x * qv.y + p12.x * qv.z + p13.x * qv.w;
        float s2 = p20.x * qv.x + p21.x * qv.y + p22.x * qv.z + p23.x * qv.w;
        float s3 = p30.x * qv.x + p31.x * qv.y + p32.x * qv.z + p33.x * qv.w;

        #pragma unroll
        for (int off = 8; off > 0; off >>= 1) {
            s0 += __shfl_xor_sync(hmask, s0, off);
            s1 += __shfl_xor_sync(hmask, s1, off);
            s2 += __shfl_xor_sync(hmask, s2, off);
            s3 += __shfl_xor_sync(hmask, s3, off);
        }

        float ex0 = __expf(s0);
        float ex1 = ok1 ? __expf(s1) : 0.0f;
        float ex2 = ok2 ? __expf(s2) : 0.0f;
        float ex3 = ok3 ? __expf(s3) : 0.0f;

        if (li == 0) {
            int j0 = i - beg;
            if (j0 < DEG_CAP) s_ex[wid][j0] = ex0; else exbuf[E0.y] = ex0;
            if (ok1) { if (j0 + 2 < DEG_CAP) s_ex[wid][j0 + 2] = ex1; else exbuf[E1.y] = ex1; }
            if (ok2) { if (j0 + 4 < DEG_CAP) s_ex[wid][j0 + 4] = ex2; else exbuf[E2.y] = ex2; }
            if (ok3) { if (j0 + 6 < DEG_CAP) s_ex[wid][j0 + 6] = ex3; else exbuf[E3.y] = ex3; }
        }

        den += (ex0 + ex1) + (ex2 + ex3);
        acc.x += ex0 * p00.y + ex1 * p10.y + ex2 * p20.y + ex3 * p30.y;
        acc.y += ex0 * p01.y + ex1 * p11.y + ex2 * p21.y + ex3 * p31.y;
        acc.z += ex0 * p02.y + ex1 * p12.y + ex2 * p22.y + ex3 * p32.y;
        acc.w += ex0 * p03.y + ex1 * p13.y + ex2 * p23.y + ex3 * p33.y;
    }

    den   += __shfl_xor_sync(0xffffffffu, den, 16);
    acc.x += __shfl_xor_sync(0xffffffffu, acc.x, 16);
    acc.y += __shfl_xor_sync(0xffffffffu, acc.y, 16);
    acc.z += __shfl_xor_sync(0xffffffffu, acc.z, 16);
    acc.w += __shfl_xor_sync(0xffffffffu, acc.w, 16);
    float rden = (den > 0.0f) ? 1.0f / den : 0.0f;

    if (cnt > DEG_CAP) __threadfence_block();     // make parked ex visible
    __syncwarp();

    // alpha writeback: all 32 lanes sweep this node's CSR range
    for (int j = lane; j < cnt; j += 32) {
        int eid = g_edges[beg + j].y;
        float ex = (j < DEG_CAP) ? s_ex[wid][j] : exbuf[eid];
        exbuf[eid] = ex * rden;
    }

    if (half == 0) {
        float4 hv = make_float4(acc.x * rden, acc.y * rden, acc.z * rden, acc.w * rden);
        *(float4*)(h + (size_t)w * D + li * 4) = hv;   // zeros for empty dst
    }
}

// ---------------------------------------------------------------------------
// Launch. Inputs: z, Wq, bq, Wk, bk, Wv, bv, src, dst.
// Output: h [N,64] floats followed by alpha [E] floats.
// Launch order (6 kernels): proj(s1 fork), hist, scan1, scan3, scatter, fused
// -> fused is launch #6 so ncu (-s 5 -c 1) profiles it next round.
// ---------------------------------------------------------------------------
extern "C" void kernel_launch(void* const* d_in, const int* in_sizes, int n_in,
                              void* d_out, int out_size)
{
    const float* z  = (const float*)d_in[0];
    const float* Wq = (const float*)d_in[1];
    const float* bq = (const float*)d_in[2];
    const float* Wk = (const float*)d_in[3];
    const float* bk = (const float*)d_in[4];
    const float* Wv = (const float*)d_in[5];
    const float* bv = (const float*)d_in[6];
    const int*  src = (const int*)d_in[7];
    const int*  dst = (const int*)d_in[8];

    const int n = in_sizes[0] / D;
    const int E = in_sizes[7];

    float* out = (float*)d_out;

    float* exbuf;
    if ((long long)out_size >= (long long)n * D + (long long)E) {
        exbuf = out + (size_t)n * D;
    } else {
        void* p = nullptr;
        cudaGetSymbolAddress(&p, g_ex);
        exbuf = (float*)p;
    }

    static cudaStream_t s1 = nullptr;
    static cudaEvent_t evF = nullptr, evJ = nullptr;
    if (s1 == nullptr) {
        cudaStreamCreateWithFlags(&s1, cudaStreamNonBlocking);
        cudaEventCreateWithFlags(&evF, cudaEventDisableTiming);
        cudaEventCreateWithFlags(&evJ, cudaEventDisableTiming);
    }

    const int len   = n + 1;
    const int nblk  = (len + SCAN_B - 1) / SCAN_B;
    const int eblk4 = (E + 1023) / 1024;   // 4 edges/thread, 256 threads

    // Fork: proj on s1, CSR chain on the main (capturing) stream.
    cudaEventRecord(evF, 0);
    cudaStreamWaitEvent(s1, evF, 0);
    proj_kernel<<<(n + 63) / 64, 256, 0, s1>>>(z, Wq, bq, Wk, bk, Wv, bv, n);
    cudaEventRecord(evJ, s1);

    hist_kernel<<<eblk4, 256>>>(dst, E);
    scan1_kernel<<<nblk, SCAN_B>>>(len);
    scan3_kernel<<<nblk, SCAN_B>>>(len);
    scatter_kernel<<<eblk4, 256>>>(src, dst, E, n);

    // Join: fused needs both q/kv (s1) and the CSR (main).
    cudaStreamWaitEvent(0, evJ, 0);
    fused_attn_kernel<<<(n + 7) / 8, 256>>>(exbuf, out, n);
}

// round 9
// speedup vs baseline: 1.1885x; 1.1885x over previous
#include <cuda_runtime.h>
#include <cuda_fp16.h>
#include <math.h>

#define MAX_N 100000
#define MAX_E 1600000
#define D 64
#define SCAN_B 1024

// ---- device scratch (no cudaMalloc allowed) --------------------------------
// g_count is zero at module load; scatter_kernel re-zeroes it every launch
// (after its last reader ran), so every launch sees zeros.
__device__ __align__(16) __half g_qh[MAX_N * D];   // q  fp16, 128B/row
__device__ __align__(16) __half g_kh[MAX_N * D];   // k*tau fp16
__device__ __align__(16) __half g_vh[MAX_N * D];   // v  fp16
__device__ int   g_count[MAX_N + 1];
__device__ int   g_rowptr[MAX_N + 1];
__device__ int   g_cursor[MAX_N + 1];
__device__ int   g_bsum[128];
__device__ int2  g_edges[MAX_E];        // (src, orig_eid) clustered by dst
__device__ float g_exc[MAX_E];          // ex in CSR order (coalesced)
__device__ float g_ex[MAX_E];           // fallback if out has no alpha slot

// ---------------------------------------------------------------------------
// K1: q,k,v = z @ W{q,k,v} + b (fp32 math), packed to fp16 rows.
// tau folded into k. 64 nodes x 64 dims per block, 4x4 register tile.
// ---------------------------------------------------------------------------
__global__ __launch_bounds__(256) void proj_kernel(
    const float* __restrict__ z,
    const float* __restrict__ Wq, const float* __restrict__ bq,
    const float* __restrict__ Wk, const float* __restrict__ bk,
    const float* __restrict__ Wv, const float* __restrict__ bv,
    int n)
{
    __shared__ __align__(16) float zsh[64 * 68];   // transposed: zsh[k*68 + node]
    __shared__ __align__(16) float wsh[64 * 64];   // wsh[k*64 + dim]

    const int tid = threadIdx.x;
    const int node0 = blockIdx.x * 64;

    for (int i = tid; i < 64 * 64; i += 256) {
        int nn = i >> 6, kk = i & 63;
        int g = node0 + nn;
        zsh[kk * 68 + nn] = (g < n) ? z[(size_t)g * D + kk] : 0.0f;
    }

    const float* Ws[3] = {Wq, Wk, Wv};
    const float* bs[3] = {bq, bk, bv};
    __half* outs[3] = {g_qh, g_kh, g_vh};

    const int ng = tid >> 4;   // node group 0..15 (4 nodes)
    const int dg = tid & 15;   // dim  group 0..15 (4 dims)

    for (int p = 0; p < 3; p++) {
        __syncthreads();
        const float* W = Ws[p];
        for (int i = tid; i < 64 * 64; i += 256) wsh[i] = W[i];
        __syncthreads();

        float4 b4 = *(const float4*)(bs[p] + dg * 4);
        float acc[4][4];
        #pragma unroll
        for (int i2 = 0; i2 < 4; i2++) {
            acc[i2][0] = b4.x; acc[i2][1] = b4.y; acc[i2][2] = b4.z; acc[i2][3] = b4.w;
        }

        #pragma unroll 8
        for (int k = 0; k < 64; k++) {
            float4 zv = *(const float4*)&zsh[k * 68 + ng * 4];
            float4 wv = *(const float4*)&wsh[k * 64 + dg * 4];
            acc[0][0] += zv.x * wv.x; acc[0][1] += zv.x * wv.y; acc[0][2] += zv.x * wv.z; acc[0][3] += zv.x * wv.w;
            acc[1][0] += zv.y * wv.x; acc[1][1] += zv.y * wv.y; acc[1][2] += zv.y * wv.z; acc[1][3] += zv.y * wv.w;
            acc[2][0] += zv.z * wv.x; acc[2][1] += zv.z * wv.y; acc[2][2] += zv.z * wv.z; acc[2][3] += zv.z * wv.w;
            acc[3][0] += zv.w * wv.x; acc[3][1] += zv.w * wv.y; acc[3][2] += zv.w * wv.z; acc[3][3] += zv.w * wv.w;
        }

        const float scl = (p == 1) ? 0.125f : 1.0f;   // tau into k
        __half* op = outs[p];
        #pragma unroll
        for (int i2 = 0; i2 < 4; i2++) {
            int g = node0 + ng * 4 + i2;
            if (g < n) {
                __half2 h01 = __float22half2_rn(make_float2(acc[i2][0] * scl, acc[i2][1] * scl));
                __half2 h23 = __float22half2_rn(make_float2(acc[i2][2] * scl, acc[i2][3] * scl));
                uint2 pk;
                pk.x = *(unsigned*)&h01; pk.y = *(unsigned*)&h23;
                *(uint2*)(op + (size_t)g * D + dg * 4) = pk;   // 8B aligned
            }
        }
    }
}

// ---------------------------------------------------------------------------
// CSR build: hist (int4) -> scan1 (block sums) -> scan3 (scan + per-block
// bsum prefix) -> scatter (int4, also re-zeroes g_count for next launch).
// ---------------------------------------------------------------------------
__global__ void hist_kernel(const int* __restrict__ dst, int E) {
    int e = (blockIdx.x * blockDim.x + threadIdx.x) * 4;
    if (e + 3 < E) {
        int4 d = *(const int4*)(dst + e);
        atomicAdd(&g_count[d.x], 1);
        atomicAdd(&g_count[d.y], 1);
        atomicAdd(&g_count[d.z], 1);
        atomicAdd(&g_count[d.w], 1);
    } else {
        for (int t = e; t < E; t++) atomicAdd(&g_count[dst[t]], 1);
    }
}

__global__ __launch_bounds__(SCAN_B) void scan1_kernel(int len) {
    __shared__ int wsum[32];
    int t = threadIdx.x, lane = t & 31, wid = t >> 5;
    int i = blockIdx.x * SCAN_B + t;
    int v = (i < len) ? g_count[i] : 0;
    #pragma unroll
    for (int off = 16; off > 0; off >>= 1) v += __shfl_xor_sync(0xffffffffu, v, off);
    if (lane == 0) wsum[wid] = v;
    __syncthreads();
    if (wid == 0) {
        int x = wsum[lane];
        #pragma unroll
        for (int off = 16; off > 0; off >>= 1) x += __shfl_xor_sync(0xffffffffu, x, off);
        if (lane == 0) g_bsum[blockIdx.x] = x;
    }
}

__global__ __launch_bounds__(SCAN_B) void scan3_kernel(int len) {
    __shared__ int wsum[32];
    __shared__ int blk_off;
    int t = threadIdx.x, lane = t & 31, wid = t >> 5;

    if (wid == 0) {
        int s = 0;
        for (int b = lane; b < blockIdx.x; b += 32) s += g_bsum[b];
        #pragma unroll
        for (int off = 16; off > 0; off >>= 1) s += __shfl_xor_sync(0xffffffffu, s, off);
        if (lane == 0) blk_off = s;
    }

    int i = blockIdx.x * SCAN_B + t;
    int v = (i < len) ? g_count[i] : 0;
    int incl = v;
    #pragma unroll
    for (int off = 1; off < 32; off <<= 1) {
        int u = __shfl_up_sync(0xffffffffu, incl, off);
        if (lane >= off) incl += u;
    }
    if (lane == 31) wsum[wid] = incl;
    __syncthreads();
    if (wid == 0) {
        int x = wsum[lane];
        #pragma unroll
        for (int off = 1; off < 32; off <<= 1) {
            int u = __shfl_up_sync(0xffffffffu, x, off);
            if (lane >= off) x += u;
        }
        wsum[lane] = x;
    }
    __syncthreads();
    int excl = incl - v + ((wid > 0) ? wsum[wid - 1] : 0) + blk_off;
    if (i < len) { g_rowptr[i] = excl; g_cursor[i] = excl; }
}

__global__ void scatter_kernel(const int* __restrict__ src,
                               const int* __restrict__ dst, int E, int n) {
    int gt = blockIdx.x * blockDim.x + threadIdx.x;
    if (gt <= n) g_count[gt] = 0;   // re-zero histogram for next launch

    int e = gt * 4;
    if (e + 3 < E) {
        int4 s = *(const int4*)(src + e);
        int4 d = *(const int4*)(dst + e);
        int p0 = atomicAdd(&g_cursor[d.x], 1);
        int p1 = atomicAdd(&g_cursor[d.y], 1);
        int p2 = atomicAdd(&g_cursor[d.z], 1);
        int p3 = atomicAdd(&g_cursor[d.w], 1);
        g_edges[p0] = make_int2(s.x, e + 0);
        g_edges[p1] = make_int2(s.y, e + 1);
        g_edges[p2] = make_int2(s.z, e + 2);
        g_edges[p3] = make_int2(s.w, e + 3);
    } else {
        for (int t = e; t < E; t++) {
            int pos = atomicAdd(&g_cursor[dst[t]], 1);
            g_edges[pos] = make_int2(src[t], t);
        }
    }
}

// ---------------------------------------------------------------------------
// K2 (fused): one warp per dst node, 8 lanes per edge, 4 edges per iteration
// processed by ONE instruction stream (4 groups of 8 lanes). fp16 HFMA2 dot
// (tau folded into k), fp32 accumulation of den and h. ex written coalesced
// to a CSR-ordered buffer; epilogue scatters alpha=ex*rden to original eids
// and stores h with two float4 per lane-group. NO atomics, NO smem.
// Segment-max skipped: alpha shift-invariant, |e|<~6 -> exp safe.
// ---------------------------------------------------------------------------
__global__ __launch_bounds__(256) void fused_attn_kernel(
    float* __restrict__ exbuf, float* __restrict__ h, int n)
{
    int wid = threadIdx.x >> 5;
    int w = blockIdx.x * 8 + wid;
    if (w >= n) return;
    int lane = threadIdx.x & 31;
    int grp  = lane >> 3;        // edge group 0..3
    int ch   = lane & 7;         // 8-half chunk of the 64-dim row

    int beg = __ldg(&g_rowptr[w]);
    int end = __ldg(&g_rowptr[w + 1]);
    int cnt = end - beg;

    // q chunk: 8 halfs = 4 half2 (lanes 8..31 broadcast the same 128B row)
    uint4 qraw = *(const uint4*)(g_qh + (size_t)w * D + ch * 8);
    __half2 q0 = *(__half2*)&qraw.x, q1 = *(__half2*)&qraw.y,
            q2 = *(__half2*)&qraw.z, q3 = *(__half2*)&qraw.w;

    float den = 0.0f;
    float acc[8];
    #pragma unroll
    for (int j = 0; j < 8; j++) acc[j] = 0.0f;

    for (int i = beg; i < end; i += 4) {
        int idx = i + grp;
        bool ok = idx < end;
        int2 er = g_edges[ok ? idx : end - 1];   // loop entered => end > beg
        int s = er.x;

        uint4 kraw = *(const uint4*)(g_kh + (size_t)s * D + ch * 8);
        uint4 vraw = *(const uint4*)(g_vh + (size_t)s * D + ch * 8);

        // fp16 dot (k pre-scaled by tau), fp32 cross-lane reduce over 8 lanes
        __half2 a = __hmul2(*(__half2*)&kraw.x, q0);
        a = __hfma2(*(__half2*)&kraw.y, q1, a);
        a = __hfma2(*(__half2*)&kraw.z, q2, a);
        a = __hfma2(*(__half2*)&kraw.w, q3, a);
        float2 f = __half22float2(a);
        float sdot = f.x + f.y;
        sdot += __shfl_xor_sync(0xffffffffu, sdot, 4);
        sdot += __shfl_xor_sync(0xffffffffu, sdot, 2);
        sdot += __shfl_xor_sync(0xffffffffu, sdot, 1);

        float ex = ok ? __expf(sdot) : 0.0f;
        den += ex;
        if (ok && ch == 0) g_exc[idx] = ex;      // 4 lanes -> 16B coalesced

        float2 v0 = __half22float2(*(__half2*)&vraw.x);
        float2 v1 = __half22float2(*(__half2*)&vraw.y);
        float2 v2 = __half22float2(*(__half2*)&vraw.z);
        float2 v3 = __half22float2(*(__half2*)&vraw.w);
        acc[0] += ex * v0.x; acc[1] += ex * v0.y;
        acc[2] += ex * v1.x; acc[3] += ex * v1.y;
        acc[4] += ex * v2.x; acc[5] += ex * v2.y;
        acc[6] += ex * v3.x; acc[7] += ex * v3.y;
    }

    // combine the 4 edge groups (chunk ch aligns across xor 8 / 16)
    den += __shfl_xor_sync(0xffffffffu, den, 8);
    den += __shfl_xor_sync(0xffffffffu, den, 16);
    #pragma unroll
    for (int j = 0; j < 8; j++) {
        acc[j] += __shfl_xor_sync(0xffffffffu, acc[j], 8);
        acc[j] += __shfl_xor_sync(0xffffffffu, acc[j], 16);
    }
    float rden = (den > 0.0f) ? 1.0f / den : 0.0f;

    if (grp == 0) {
        float4 h0 = make_float4(acc[0] * rden, acc[1] * rden, acc[2] * rden, acc[3] * rden);
        float4 h1 = make_float4(acc[4] * rden, acc[5] * rden, acc[6] * rden, acc[7] * rden);
        *(float4*)(h + (size_t)w * D + ch * 8)     = h0;   // zeros for empty dst
        *(float4*)(h + (size_t)w * D + ch * 8 + 4) = h1;
    }

    // alpha writeback: sweep CSR range (coalesced reads, scattered stores)
    for (int j = lane; j < cnt; j += 32) {
        int eid = g_edges[beg + j].y;
        exbuf[eid] = g_exc[beg + j] * rden;
    }
}

// ---------------------------------------------------------------------------
// Launch. Inputs: z, Wq, bq, Wk, bk, Wv, bv, src, dst.
// Output: h [N,64] floats followed by alpha [E] floats.
// proj forked onto a second stream (captured fork-join); CSR chain on main.
// ---------------------------------------------------------------------------
extern "C" void kernel_launch(void* const* d_in, const int* in_sizes, int n_in,
                              void* d_out, int out_size)
{
    const float* z  = (const float*)d_in[0];
    const float* Wq = (const float*)d_in[1];
    const float* bq = (const float*)d_in[2];
    const float* Wk = (const float*)d_in[3];
    const float* bk = (const float*)d_in[4];
    const float* Wv = (const float*)d_in[5];
    const float* bv = (const float*)d_in[6];
    const int*  src = (const int*)d_in[7];
    const int*  dst = (const int*)d_in[8];

    const int n = in_sizes[0] / D;
    const int E = in_sizes[7];

    float* out = (float*)d_out;

    float* exbuf;
    if ((long long)out_size >= (long long)n * D + (long long)E) {
        exbuf = out + (size_t)n * D;
    } else {
        void* p = nullptr;
        cudaGetSymbolAddress(&p, g_ex);
        exbuf = (float*)p;
    }

    static cudaStream_t s1 = nullptr;
    static cudaEvent_t evF = nullptr, evJ = nullptr;
    if (s1 == nullptr) {
        cudaStreamCreateWithFlags(&s1, cudaStreamNonBlocking);
        cudaEventCreateWithFlags(&evF, cudaEventDisableTiming);
        cudaEventCreateWithFlags(&evJ, cudaEventDisableTiming);
    }

    const int len   = n + 1;
    const int nblk  = (len + SCAN_B - 1) / SCAN_B;
    const int eblk4 = (E + 1023) / 1024;   // 4 edges/thread, 256 threads

    // Fork: proj on s1, CSR chain on the main (capturing) stream.
    cudaEventRecord(evF, 0);
    cudaStreamWaitEvent(s1, evF, 0);
    proj_kernel<<<(n + 63) / 64, 256, 0, s1>>>(z, Wq, bq, Wk, bk, Wv, bv, n);
    cudaEventRecord(evJ, s1);

    hist_kernel<<<eblk4, 256>>>(dst, E);
    scan1_kernel<<<nblk, SCAN_B>>>(len);
    scan3_kernel<<<nblk, SCAN_B>>>(len);
    scatter_kernel<<<eblk4, 256>>>(src, dst, E, n);

    // Join: fused needs both q/k/v (s1) and the CSR (main).
    cudaStreamWaitEvent(0, evJ, 0);
    fused_attn_kernel<<<(n + 7) / 8, 256>>>(exbuf, out, n);
}